// round 5
// baseline (speedup 1.0000x reference)
#include <cuda_runtime.h>
#include <cuda_bf16.h>

// QuaternionPositionToMatrixLayer: x[B,7] f32 -> pose[B,3,4] f32
//   row: q0 q1 q2 q3 tx ty tz  ->  [R | t] (3x4, row-major)
//
// Strategy: SMEM-staged tile (256 rows/block) so ALL global traffic is
// contiguous float4 (LDG.128 / STG.128). Avoids the 7x L1tex wavefront
// inflation of strided per-row scalar access. Pure HBM-bound: 304 MB total.

constexpr int TPB = 256;                 // rows per block == threads per block
constexpr int IN_F4_PER_TILE  = TPB * 7 / 4;   // 448 float4 of input per tile
constexpr int OUT_F4_PER_TILE = TPB * 12 / 4;  // 768 float4 of output per tile

__global__ void __launch_bounds__(TPB)
quat_pose_kernel(const float4* __restrict__ in4,
                 float4* __restrict__ out4,
                 int nrows)
{
    __shared__ float4 s_in4[IN_F4_PER_TILE];    // 7168 B
    __shared__ float4 s_out4[OUT_F4_PER_TILE];  // 12288 B

    const int block_row0 = blockIdx.x * TPB;
    const int tid = threadIdx.x;

    // ---- Phase 1: coalesced tile load (contiguous float4) ----
    {
        const long long in4_total = (long long)nrows * 7 / 4;
        const long long base4 = (long long)block_row0 * 7 / 4;
        #pragma unroll
        for (int i = tid; i < IN_F4_PER_TILE; i += TPB) {
            if (base4 + i < in4_total) {
                s_in4[i] = in4[base4 + i];
            }
        }
    }
    __syncthreads();

    // ---- Phase 2: per-thread compute (conflict-free LDS: stride 7 words) ----
    if (block_row0 + tid < nrows) {
        const float* s_in = reinterpret_cast<const float*>(s_in4);
        const int o = tid * 7;
        const float q0 = s_in[o + 0];
        const float q1 = s_in[o + 1];
        const float q2 = s_in[o + 2];
        const float q3 = s_in[o + 3];
        const float tx = s_in[o + 4];
        const float ty = s_in[o + 5];
        const float tz = s_in[o + 6];

        const float q00 = q0 * q0, q11 = q1 * q1, q22 = q2 * q2, q33 = q3 * q3;
        const float q01 = q0 * q1, q02 = q0 * q2, q03 = q0 * q3;
        const float q12 = q1 * q2, q13 = q1 * q3, q23 = q2 * q3;

        float4 r0, r1, r2;
        r0.x = q00 + q11 - q22 - q33;
        r0.y = 2.0f * q12 - 2.0f * q03;
        r0.z = 2.0f * q13 + 2.0f * q02;
        r0.w = tx;
        r1.x = 2.0f * q12 + 2.0f * q03;
        r1.y = q00 - q11 + q22 - q33;
        r1.z = 2.0f * q23 - 2.0f * q01;
        r1.w = ty;
        r2.x = 2.0f * q13 - 2.0f * q02;
        r2.y = 2.0f * q23 + 2.0f * q01;
        r2.z = q00 - q11 - q22 + q33;
        r2.w = tz;

        // STS.128 x3 at 48B thread stride (12-word): distinct banks per
        // quarter-warp phase -> effectively conflict-free.
        s_out4[tid * 3 + 0] = r0;
        s_out4[tid * 3 + 1] = r1;
        s_out4[tid * 3 + 2] = r2;
    }
    __syncthreads();

    // ---- Phase 3: coalesced tile store (contiguous float4) ----
    {
        const long long out4_total = (long long)nrows * 3;
        const long long obase4 = (long long)block_row0 * 3;
        #pragma unroll
        for (int i = tid; i < OUT_F4_PER_TILE; i += TPB) {
            if (obase4 + i < out4_total) {
                out4[obase4 + i] = s_out4[i];
            }
        }
    }
}

extern "C" void kernel_launch(void* const* d_in, const int* in_sizes, int n_in,
                              void* d_out, int out_size)
{
    const float4* in4 = reinterpret_cast<const float4*>(d_in[0]);
    float4* out4 = reinterpret_cast<float4*>(d_out);

    const int n_floats = in_sizes[0];     // B * 7
    const int nrows = n_floats / 7;       // B (4,000,000)

    const int nblocks = (nrows + TPB - 1) / TPB;   // 15625 for B=4M
    quat_pose_kernel<<<nblocks, TPB>>>(in4, out4, nrows);
}